// round 1
// baseline (speedup 1.0000x reference)
#include <cuda_runtime.h>
#include <cstdint>

// Problem constants (fixed by the dataset)
#define T_LEN   4096
#define D_DIM   64
#define R_OUT   127
#define HALF_W  63

// Tiling
#define TT      128                 // t rows per block
#define SROWS   (TT + 126)          // k halo rows = 254
#define QSTRIDE 129                 // float2 units, ≡1 mod 16 (conflict-free staging)
#define KSTRIDE 289                 // float2 units, ≥ p(253)+1 = 285, ≡1 mod 16
#define Q_F2    (32 * QSTRIDE)      // 4128 float2
#define K_F2    (32 * KSTRIDE)      // 9248 float2
#define SMEM_BYTES ((Q_F2 + K_F2) * (int)sizeof(float2))   // 107008 B

// Blackwell packed dual-FMA: d.lo += a.lo*b.lo ; d.hi += a.hi*b.hi
#define FFMA2(d, a, b) \
    asm("fma.rn.f32x2 %0, %1, %2, %0;" : "+l"(d) : "l"(a), "l"(b))

__global__ void __launch_bounds__(256, 1)
unfold_dot_kernel(const float* __restrict__ q,
                  const float* __restrict__ k,
                  float* __restrict__ out)
{
    extern __shared__ float2 smem[];
    float2* q_s = smem;          // [32][QSTRIDE]  d2-major, element = (d, d+1) pair
    float2* k_s = smem + Q_F2;   // [32][KSTRIDE]  d2-major, s index skewed: p(s)=s+(s>>3)

    const int tid = threadIdx.x;
    const int t0  = blockIdx.x * TT;
    const int bh  = blockIdx.y;

    // ---- stage q tile: [TT][64] -> d-major float2, transposed ----
    const float4* qg = reinterpret_cast<const float4*>(q) +
                       ((size_t)bh * T_LEN + t0) * (D_DIM / 4);
    #pragma unroll
    for (int it = 0; it < (TT * 16) / 256; ++it) {
        int idx = tid + it * 256;
        int row = idx >> 4;
        int d4  = idx & 15;
        float4 v = qg[row * 16 + d4];
        q_s[(2 * d4    ) * QSTRIDE + row] = make_float2(v.x, v.y);
        q_s[(2 * d4 + 1) * QSTRIDE + row] = make_float2(v.z, v.w);
    }

    // ---- stage k halo tile: s in [t0-63, t0+190], zero-padded, skewed ----
    const float4* kg = reinterpret_cast<const float4*>(k) +
                       (size_t)bh * T_LEN * (D_DIM / 4);
    for (int idx = tid; idx < SROWS * 16; idx += 256) {
        int s_local = idx >> 4;
        int d4      = idx & 15;
        int s_glob  = t0 - HALF_W + s_local;
        float4 v = make_float4(0.f, 0.f, 0.f, 0.f);
        if (s_glob >= 0 && s_glob < T_LEN) v = kg[s_glob * 16 + d4];
        int p = s_local + (s_local >> 3);            // bank skew
        k_s[(2 * d4    ) * KSTRIDE + p] = make_float2(v.x, v.y);
        k_s[(2 * d4 + 1) * KSTRIDE + p] = make_float2(v.z, v.w);
    }
    __syncthreads();

    // ---- register-tiled compute: thread = 8 t x 8 r, d packed in f32x2 ----
    const int tg    = tid >> 4;          // 0..15
    const int rg    = tid & 15;          // 0..15
    const int tbase = tg * 8;
    const int sbase = tbase + rg * 8;    // multiple of 8 -> skew folds into pbase
    const int pbase = sbase + (sbase >> 3);

    unsigned long long acc[8][8];
    #pragma unroll
    for (int i = 0; i < 8; ++i)
        #pragma unroll
        for (int j = 0; j < 8; ++j) acc[i][j] = 0ull;

    const float2* qp = q_s + tbase;
    const float2* kp = k_s + pbase;

    #pragma unroll 1
    for (int d2 = 0; d2 < 32; ++d2) {
        unsigned long long kv[15], qv[8];
        #pragma unroll
        for (int m = 0; m < 15; ++m)      // immediates: m + (m>>3) is constexpr
            kv[m] = *reinterpret_cast<const unsigned long long*>(kp + m + (m >> 3));
        #pragma unroll
        for (int i = 0; i < 8; ++i)
            qv[i] = *reinterpret_cast<const unsigned long long*>(qp + i);

        #pragma unroll
        for (int i = 0; i < 8; ++i)
            #pragma unroll
            for (int j = 0; j < 8; ++j)
                FFMA2(acc[i][j], qv[i], kv[i + j]);

        qp += QSTRIDE;
        kp += KSTRIDE;
    }

    // ---- epilogue: reduce f32x2 pair, store band (skip r == 127) ----
    const int rbase = rg * 8;
    #pragma unroll
    for (int i = 0; i < 8; ++i) {
        float* op = out + ((size_t)bh * T_LEN + t0 + tbase + i) * R_OUT + rbase;
        #pragma unroll
        for (int j = 0; j < 8; ++j) {
            if (rbase + j < R_OUT) {
                float2 f = *reinterpret_cast<float2*>(&acc[i][j]);
                op[j] = f.x + f.y;
            }
        }
    }
}

extern "C" void kernel_launch(void* const* d_in, const int* in_sizes, int n_in,
                              void* d_out, int out_size)
{
    const float* q = (const float*)d_in[0];
    const float* k = (const float*)d_in[1];
    float* out     = (float*)d_out;

    // BH derived from input size for robustness (B*H*T*D elements)
    int bh = in_sizes[0] / (T_LEN * D_DIM);   // = 128

    cudaFuncSetAttribute(unfold_dot_kernel,
                         cudaFuncAttributeMaxDynamicSharedMemorySize, SMEM_BYTES);

    dim3 grid(T_LEN / TT, bh);
    unfold_dot_kernel<<<grid, 256, SMEM_BYTES>>>(q, k, out);
}

// round 3
// speedup vs baseline: 3.1980x; 3.1980x over previous
#include <cuda_runtime.h>
#include <cuda_bf16.h>
#include <cstdint>

// Problem constants
#define T_LEN   4096
#define D_DIM   64
#define R_OUT   127
#define HALF_W  63

#define TT      128      // t rows per tile (M)
#define NS      256      // k halo rows staged (N); rows 254..255 zero
#define SROWS   254

// SMEM layout (bf16 tiles, 128 B per row, SW128-style 16B swizzle)
#define SM_A_HI   0
#define SM_A_LO   (SM_A_HI + TT * 128)      // 16384
#define SM_B_HI   (SM_A_LO + TT * 128)      // 32768
#define SM_B_LO   (SM_B_HI + NS * 128)      // 65536
#define SM_TOTAL  (SM_B_LO + NS * 128)      // 98304
#define SM_BAND   0                          // aliased after compute (65024 B)

#define BAND_BYTES (TT * R_OUT * 4)

#define SWZ(off) ((off) ^ (((off) >> 3) & 0x70))

static __device__ __forceinline__ uint32_t smem_u32(const void* p) {
    uint32_t a;
    asm("{ .reg .u64 t; cvta.to.shared.u64 t, %1; cvt.u32.u64 %0, t; }" : "=r"(a) : "l"(p));
    return a;
}

// fp32x4 -> packed bf16x2 hi pair + residual lo pair
static __device__ __forceinline__ void split4(float4 v, uint32_t& h0, uint32_t& h1,
                                              uint32_t& l0, uint32_t& l1) {
    asm("cvt.rn.bf16x2.f32 %0, %1, %2;" : "=r"(h0) : "f"(v.y), "f"(v.x));
    asm("cvt.rn.bf16x2.f32 %0, %1, %2;" : "=r"(h1) : "f"(v.w), "f"(v.z));
    float rx = v.x - __uint_as_float(h0 << 16);
    float ry = v.y - __uint_as_float(h0 & 0xffff0000u);
    float rz = v.z - __uint_as_float(h1 << 16);
    float rw = v.w - __uint_as_float(h1 & 0xffff0000u);
    asm("cvt.rn.bf16x2.f32 %0, %1, %2;" : "=r"(l0) : "f"(ry), "f"(rx));
    asm("cvt.rn.bf16x2.f32 %0, %1, %2;" : "=r"(l1) : "f"(rw), "f"(rz));
}

#define LDSM_X4(r0, r1, r2, r3, a) \
    asm volatile("ldmatrix.sync.aligned.m8n8.x4.shared.b16 {%0,%1,%2,%3}, [%4];" \
        : "=r"(r0), "=r"(r1), "=r"(r2), "=r"(r3) : "r"(a))

#define LDSM_X2(r0, r1, a) \
    asm volatile("ldmatrix.sync.aligned.m8n8.x2.shared.b16 {%0,%1}, [%2];" \
        : "=r"(r0), "=r"(r1) : "r"(a))

#define MMA16816(d, a0, a1, a2, a3, b0, b1) \
    asm volatile("mma.sync.aligned.m16n8k16.row.col.f32.bf16.bf16.f32 " \
        "{%0,%1,%2,%3}, {%4,%5,%6,%7}, {%8,%9}, {%0,%1,%2,%3};" \
        : "+f"(d[0]), "+f"(d[1]), "+f"(d[2]), "+f"(d[3]) \
        : "r"(a0), "r"(a1), "r"(a2), "r"(a3), "r"(b0), "r"(b1))

__global__ void __launch_bounds__(256, 1)
unfold_dot_hmma(const float* __restrict__ q,
                const float* __restrict__ k,
                float* __restrict__ out)
{
    extern __shared__ char smem[];
    const uint32_t sb = smem_u32(smem);
    const int tid = threadIdx.x;
    const int wid = tid >> 5;
    const int lid = tid & 31;
    const int t0  = blockIdx.x * TT;
    const int bh  = blockIdx.y;

    // ---- stage Q tile: 128 rows x 64 d -> bf16 hi/lo, swizzled rows of 128B ----
    const float4* qg = reinterpret_cast<const float4*>(q) +
                       ((size_t)bh * T_LEN + t0) * (D_DIM / 4);
    #pragma unroll
    for (int it = 0; it < 4; ++it) {
        int idx = tid + it * 256;          // 0..1023
        int row = idx >> 3;
        int g   = idx & 7;                 // 16B chunk within row
        float4 v0 = qg[row * 16 + g * 2];
        float4 v1 = qg[row * 16 + g * 2 + 1];
        uint32_t h0, h1, h2, h3, l0, l1, l2, l3;
        split4(v0, h0, h1, l0, l1);
        split4(v1, h2, h3, l2, l3);
        uint32_t off = SWZ((uint32_t)(row * 128 + g * 16));
        *reinterpret_cast<uint4*>(smem + SM_A_HI + off) = make_uint4(h0, h1, h2, h3);
        *reinterpret_cast<uint4*>(smem + SM_A_LO + off) = make_uint4(l0, l1, l2, l3);
    }

    // ---- stage K halo: 256 rows (s = t0-63+srow), zero outside [0,T) ----
    const float4* kg = reinterpret_cast<const float4*>(k) +
                       (size_t)bh * T_LEN * (D_DIM / 4);
    #pragma unroll
    for (int it = 0; it < 8; ++it) {
        int idx  = tid + it * 256;         // 0..2047
        int srow = idx >> 3;
        int g    = idx & 7;
        int sg   = t0 - HALF_W + srow;
        float4 v0 = make_float4(0.f, 0.f, 0.f, 0.f);
        float4 v1 = v0;
        if (srow < SROWS && (unsigned)sg < T_LEN) {
            v0 = kg[sg * 16 + g * 2];
            v1 = kg[sg * 16 + g * 2 + 1];
        }
        uint32_t h0, h1, h2, h3, l0, l1, l2, l3;
        split4(v0, h0, h1, l0, l1);
        split4(v1, h2, h3, l2, l3);
        uint32_t off = SWZ((uint32_t)(srow * 128 + g * 16));
        *reinterpret_cast<uint4*>(smem + SM_B_HI + off) = make_uint4(h0, h1, h2, h3);
        *reinterpret_cast<uint4*>(smem + SM_B_LO + off) = make_uint4(l0, l1, l2, l3);
    }
    __syncthreads();

    // ---- compute: warp w owns rows [16w,16w+16), band col tiles c=2w+j, j<18 ----
    const int m0 = wid * 16;

    // A fragments for all 4 k16-chunks, hi and lo
    uint32_t Ah[4][4], Al[4][4];
    {
        int mat = lid >> 3, r = lid & 7;
        int arow = m0 + (mat & 1) * 8 + r;
        int acb  = (mat >> 1) * 16;                 // +0 / +16 bytes
        #pragma unroll
        for (int kc = 0; kc < 4; ++kc) {
            uint32_t off = SWZ((uint32_t)(arow * 128 + kc * 32 + acb));
            LDSM_X4(Ah[kc][0], Ah[kc][1], Ah[kc][2], Ah[kc][3], sb + SM_A_HI + off);
            LDSM_X2(Al[kc][0], Al[kc][1], sb + SM_A_LO + off);
            // x2 only fills 2 regs; reload full x4 for lo:
        }
        #pragma unroll
        for (int kc = 0; kc < 4; ++kc) {
            uint32_t off = SWZ((uint32_t)(arow * 128 + kc * 32 + acb));
            LDSM_X4(Al[kc][0], Al[kc][1], Al[kc][2], Al[kc][3], sb + SM_A_LO + off);
        }
    }

    float acc[18][4];
    #pragma unroll
    for (int j = 0; j < 18; ++j)
        #pragma unroll
        for (int e = 0; e < 4; ++e) acc[j][e] = 0.f;

    const int lsel = lid & 15;
    const int brow_in = lsel & 7;
    const int bcb     = (lsel >> 3) * 16;           // +0 / +16 bytes (k8..15)

    #pragma unroll
    for (int j = 0; j < 18; ++j) {
        int n0 = m0 + j * 8;                        // 8*(2w + j)... = 16w + 8j
        int brow = n0 + brow_in;
        uint32_t base = (uint32_t)(brow * 128 + bcb);
        uint32_t bh0, bh1, bl0, bl1;
        #pragma unroll
        for (int kc = 0; kc < 4; ++kc) {
            uint32_t off = SWZ(base + kc * 32);
            LDSM_X2(bh0, bh1, sb + SM_B_HI + off);
            LDSM_X2(bl0, bl1, sb + SM_B_LO + off);
            MMA16816(acc[j], Ah[kc][0], Ah[kc][1], Ah[kc][2], Ah[kc][3], bh0, bh1);
            MMA16816(acc[j], Ah[kc][0], Ah[kc][1], Ah[kc][2], Ah[kc][3], bl0, bl1);
            MMA16816(acc[j], Al[kc][0], Al[kc][1], Al[kc][2], Al[kc][3], bh0, bh1);
        }
    }

    __syncthreads();   // all warps done reading operand smem

    // ---- epilogue: scatter band elements into smem band tile ----
    // D frag: {d0,d1}=D[l/4][(l%4)*2 +0/1], {d2,d3}=D[l/4+8][same]
    float* band = reinterpret_cast<float*>(smem + SM_BAND);
    {
        int r0 = m0 + (lid >> 2);
        int c0 = (lid & 3) * 2;
        #pragma unroll
        for (int j = 0; j < 18; ++j) {
            int n0 = m0 + j * 8;
            #pragma unroll
            for (int e = 0; e < 4; ++e) {
                int i   = r0 + (e >> 1) * 8;
                int col = n0 + c0 + (e & 1);
                unsigned rr = (unsigned)(col - i);
                if (rr < R_OUT)
                    band[i * (R_OUT - 1) + col] = acc[j][e];  // = i*127 + rr
            }
        }
    }

    asm volatile("fence.proxy.async.shared::cta;" ::: "memory");
    __syncthreads();

    // ---- one contiguous bulk store of the 128x127 band slice ----
    if (tid == 0) {
        float* dst = out + ((size_t)bh * T_LEN + t0) * R_OUT;
        asm volatile("cp.async.bulk.global.shared::cta.bulk_group [%0], [%1], %2;"
                     :: "l"(dst), "r"(sb + SM_BAND), "r"((uint32_t)BAND_BYTES) : "memory");
        asm volatile("cp.async.bulk.commit_group;" ::: "memory");
        asm volatile("cp.async.bulk.wait_group 0;" ::: "memory");
    }
}

extern "C" void kernel_launch(void* const* d_in, const int* in_sizes, int n_in,
                              void* d_out, int out_size)
{
    const float* q = (const float*)d_in[0];
    const float* k = (const float*)d_in[1];
    float* out     = (float*)d_out;

    int bh = in_sizes[0] / (T_LEN * D_DIM);   // 128

    cudaFuncSetAttribute(unfold_dot_hmma,
                         cudaFuncAttributeMaxDynamicSharedMemorySize, SM_TOTAL);

    dim3 grid(T_LEN / TT, bh);
    unfold_dot_hmma<<<grid, 256, SM_TOTAL>>>(q, k, out);
}

// round 4
// speedup vs baseline: 4.0535x; 1.2675x over previous
#include <cuda_runtime.h>
#include <cuda_bf16.h>
#include <cstdint>

// Problem constants
#define T_LEN   4096
#define D_DIM   64
#define R_OUT   127
#define HALF_W  63

#define TT      128      // t rows per tile (M)
#define NS      256      // k halo rows staged (N); rows 254..255 zero
#define SROWS   254

// SMEM layout (bf16 tiles, 128 B per row, SW128-style 16B swizzle)
#define SM_A_HI   0
#define SM_A_LO   (SM_A_HI + TT * 128)      // 16384
#define SM_B_HI   (SM_A_LO + TT * 128)      // 32768
#define SM_B_LO   (SM_B_HI + NS * 128)      // 65536
#define SM_TOTAL  (SM_B_LO + NS * 128)      // 98304
#define SM_BAND   0                          // aliased after compute (65024 B)

#define BAND_BYTES (TT * R_OUT * 4)

#define SWZ(off) ((off) ^ (((off) >> 3) & 0x70))

static __device__ __forceinline__ uint32_t smem_u32(const void* p) {
    uint32_t a;
    asm("{ .reg .u64 t; cvta.to.shared.u64 t, %1; cvt.u32.u64 %0, t; }" : "=r"(a) : "l"(p));
    return a;
}

// fp32x4 -> packed bf16x2 hi pair + residual lo pair
static __device__ __forceinline__ void split4(float4 v, uint32_t& h0, uint32_t& h1,
                                              uint32_t& l0, uint32_t& l1) {
    asm("cvt.rn.bf16x2.f32 %0, %1, %2;" : "=r"(h0) : "f"(v.y), "f"(v.x));
    asm("cvt.rn.bf16x2.f32 %0, %1, %2;" : "=r"(h1) : "f"(v.w), "f"(v.z));
    float rx = v.x - __uint_as_float(h0 << 16);
    float ry = v.y - __uint_as_float(h0 & 0xffff0000u);
    float rz = v.z - __uint_as_float(h1 << 16);
    float rw = v.w - __uint_as_float(h1 & 0xffff0000u);
    asm("cvt.rn.bf16x2.f32 %0, %1, %2;" : "=r"(l0) : "f"(ry), "f"(rx));
    asm("cvt.rn.bf16x2.f32 %0, %1, %2;" : "=r"(l1) : "f"(rw), "f"(rz));
}

#define LDSM_X4(r0, r1, r2, r3, a) \
    asm volatile("ldmatrix.sync.aligned.m8n8.x4.shared.b16 {%0,%1,%2,%3}, [%4];" \
        : "=r"(r0), "=r"(r1), "=r"(r2), "=r"(r3) : "r"(a))

#define MMA16816(d, a0, a1, a2, a3, b0, b1) \
    asm volatile("mma.sync.aligned.m16n8k16.row.col.f32.bf16.bf16.f32 " \
        "{%0,%1,%2,%3}, {%4,%5,%6,%7}, {%8,%9}, {%0,%1,%2,%3};" \
        : "+f"(d[0]), "+f"(d[1]), "+f"(d[2]), "+f"(d[3]) \
        : "r"(a0), "r"(a1), "r"(a2), "r"(a3), "r"(b0), "r"(b1))

__global__ void __launch_bounds__(256, 2)
unfold_dot_hmma(const float* __restrict__ q,
                const float* __restrict__ k,
                float* __restrict__ out)
{
    extern __shared__ char smem[];
    const uint32_t sb = smem_u32(smem);
    const int tid = threadIdx.x;
    const int wid = tid >> 5;
    const int lid = tid & 31;
    const int t0  = blockIdx.x * TT;
    const int bh  = blockIdx.y;

    // ---- stage Q tile: 128 rows x 64 d -> bf16 hi/lo, swizzled rows of 128B ----
    const float4* qg = reinterpret_cast<const float4*>(q) +
                       ((size_t)bh * T_LEN + t0) * (D_DIM / 4);
    #pragma unroll
    for (int it = 0; it < 4; ++it) {
        int idx = tid + it * 256;          // 0..1023
        int row = idx >> 3;
        int g   = idx & 7;                 // 16B chunk within row
        float4 v0 = qg[row * 16 + g * 2];
        float4 v1 = qg[row * 16 + g * 2 + 1];
        uint32_t h0, h1, h2, h3, l0, l1, l2, l3;
        split4(v0, h0, h1, l0, l1);
        split4(v1, h2, h3, l2, l3);
        uint32_t off = SWZ((uint32_t)(row * 128 + g * 16));
        *reinterpret_cast<uint4*>(smem + SM_A_HI + off) = make_uint4(h0, h1, h2, h3);
        *reinterpret_cast<uint4*>(smem + SM_A_LO + off) = make_uint4(l0, l1, l2, l3);
    }

    // ---- stage K halo: 256 rows (s = t0-63+srow), zero outside [0,T) ----
    const float4* kg = reinterpret_cast<const float4*>(k) +
                       (size_t)bh * T_LEN * (D_DIM / 4);
    #pragma unroll
    for (int it = 0; it < 8; ++it) {
        int idx  = tid + it * 256;         // 0..2047
        int srow = idx >> 3;
        int g    = idx & 7;
        int sg   = t0 - HALF_W + srow;
        float4 v0 = make_float4(0.f, 0.f, 0.f, 0.f);
        float4 v1 = v0;
        if (srow < SROWS && (unsigned)sg < T_LEN) {
            v0 = kg[sg * 16 + g * 2];
            v1 = kg[sg * 16 + g * 2 + 1];
        }
        uint32_t h0, h1, h2, h3, l0, l1, l2, l3;
        split4(v0, h0, h1, l0, l1);
        split4(v1, h2, h3, l2, l3);
        uint32_t off = SWZ((uint32_t)(srow * 128 + g * 16));
        *reinterpret_cast<uint4*>(smem + SM_B_HI + off) = make_uint4(h0, h1, h2, h3);
        *reinterpret_cast<uint4*>(smem + SM_B_LO + off) = make_uint4(l0, l1, l2, l3);
    }
    __syncthreads();

    // ---- compute: warp w owns rows [16w,16w+16), band col tiles j=0..17 at n0=m0+8j
    const int m0 = wid * 16;

    float acc[18][4];
    #pragma unroll
    for (int j = 0; j < 18; ++j)
        #pragma unroll
        for (int e = 0; e < 4; ++e) acc[j][e] = 0.f;

    // A lane address (ldmatrix x4: m0=r0-7/k0-7, m1=r8-15/k0-7, m2=r0-7/k8-15, m3=r8-15/k8-15)
    const int amat = lid >> 3;
    const uint32_t a_base = (uint32_t)((m0 + (amat & 1) * 8 + (lid & 7)) * 128
                                       + (amat >> 1) * 16);
    // B lane address (x4 over two adjacent n8 tiles):
    //   m0 = rows n0+0..7 k0-7, m1 = rows n0+0..7 k8-15,
    //   m2 = rows n0+8..15 k0-7, m3 = rows n0+8..15 k8-15
    const int bg = lid >> 3;
    const uint32_t b_base = (uint32_t)((m0 + (bg >> 1) * 8 + (lid & 7)) * 128
                                       + (bg & 1) * 16);

    #pragma unroll
    for (int kc = 0; kc < 4; ++kc) {
        uint32_t ah0, ah1, ah2, ah3, al0, al1, al2, al3;
        uint32_t aoff = SWZ(a_base + kc * 32);
        LDSM_X4(ah0, ah1, ah2, ah3, sb + SM_A_HI + aoff);
        LDSM_X4(al0, al1, al2, al3, sb + SM_A_LO + aoff);

        uint32_t boff = SWZ(b_base + kc * 32);    // jp steps add 2048: swizzle-invariant
        #pragma unroll
        for (int jp = 0; jp < 9; ++jp) {
            uint32_t bh0, bh1, bh2, bh3, bl0, bl1, bl2, bl3;
            LDSM_X4(bh0, bh1, bh2, bh3, sb + SM_B_HI + boff);
            LDSM_X4(bl0, bl1, bl2, bl3, sb + SM_B_LO + boff);
            // tile j = 2jp
            MMA16816(acc[2 * jp], ah0, ah1, ah2, ah3, bh0, bh1);
            MMA16816(acc[2 * jp], ah0, ah1, ah2, ah3, bl0, bl1);
            MMA16816(acc[2 * jp], al0, al1, al2, al3, bh0, bh1);
            // tile j = 2jp+1
            MMA16816(acc[2 * jp + 1], ah0, ah1, ah2, ah3, bh2, bh3);
            MMA16816(acc[2 * jp + 1], ah0, ah1, ah2, ah3, bl2, bl3);
            MMA16816(acc[2 * jp + 1], al0, al1, al2, al3, bh2, bh3);
            boff += 16 * 128;
        }
    }

    __syncthreads();   // all warps done reading operand smem

    // ---- epilogue: scatter band elements into smem band tile ----
    // D frag: {d0,d1}=D[l/4][(l%4)*2 +0/1], {d2,d3}=D[l/4+8][same]
    float* band = reinterpret_cast<float*>(smem + SM_BAND);
    {
        int r0 = m0 + (lid >> 2);
        int c0 = (lid & 3) * 2;
        #pragma unroll
        for (int j = 0; j < 18; ++j) {
            int n0 = m0 + j * 8;
            #pragma unroll
            for (int e = 0; e < 4; ++e) {
                int i   = r0 + (e >> 1) * 8;
                int col = n0 + c0 + (e & 1);
                unsigned rr = (unsigned)(col - i);
                if (rr < R_OUT)
                    band[i * (R_OUT - 1) + col] = acc[j][e];  // = i*127 + rr
            }
        }
    }

    asm volatile("fence.proxy.async.shared::cta;" ::: "memory");
    __syncthreads();

    // ---- one contiguous bulk store of the 128x127 band slice ----
    if (tid == 0) {
        float* dst = out + ((size_t)bh * T_LEN + t0) * R_OUT;
        asm volatile("cp.async.bulk.global.shared::cta.bulk_group [%0], [%1], %2;"
                     :: "l"(dst), "r"(sb + SM_BAND), "r"((uint32_t)BAND_BYTES) : "memory");
        asm volatile("cp.async.bulk.commit_group;" ::: "memory");
        asm volatile("cp.async.bulk.wait_group 0;" ::: "memory");
    }
}

extern "C" void kernel_launch(void* const* d_in, const int* in_sizes, int n_in,
                              void* d_out, int out_size)
{
    const float* q = (const float*)d_in[0];
    const float* k = (const float*)d_in[1];
    float* out     = (float*)d_out;

    int bh = in_sizes[0] / (T_LEN * D_DIM);   // 128

    cudaFuncSetAttribute(unfold_dot_hmma,
                         cudaFuncAttributeMaxDynamicSharedMemorySize, SM_TOTAL);

    dim3 grid(T_LEN / TT, bh);
    unfold_dot_hmma<<<grid, 256, SM_TOTAL>>>(q, k, out);
}